// round 1
// baseline (speedup 1.0000x reference)
#include <cuda_runtime.h>
#include <cstdint>

#define BB 8
#define CC 64
#define NN 4096
#define KK 20
#define OUTC 64

// ---------------- device scratch (static, allocation-free) ----------------
__device__ float g_sq[BB * NN];                    // squared norms
__device__ int   g_idx[BB * NN * KK];              // knn indices
__device__ float g_u[(size_t)BB * NN * OUTC];      // W1 @ x, point-major [p][o]
__device__ float g_v[(size_t)BB * NN * OUTC];      // (W2-W1) @ x, point-major
__device__ float g_mx[(size_t)BB * NN * OUTC];     // max_k z
__device__ float g_mn[(size_t)BB * NN * OUTC];     // min_k z
__device__ float g_sum[OUTC];
__device__ float g_sumsq[OUTC];
__device__ float g_s[OUTC];
__device__ float g_t[OUTC];

// ---------------- kernel A: squared norms + zero stats ----------------
__global__ void __launch_bounds__(128) prep_kernel(const float* __restrict__ x) {
    int p = blockIdx.x * 128 + threadIdx.x;       // p in [0, B*N)
    int b = p >> 12;
    int n = p & (NN - 1);
    const float* xb = x + (size_t)b * CC * NN + n;
    float s = 0.f;
#pragma unroll
    for (int ch = 0; ch < CC; ch++) {
        float v = xb[(size_t)ch * NN];
        s = fmaf(v, v, s);
    }
    g_sq[p] = s;
    if (blockIdx.x == 0 && threadIdx.x < OUTC) {
        g_sum[threadIdx.x] = 0.f;
        g_sumsq[threadIdx.x] = 0.f;
    }
}

// ---------------- kernel B: fused distance GEMM + top-K ----------------
__device__ __forceinline__ void heap_insert(float sc, int c, float* hD, int* hI, int tid) {
    // max-heap of size KK, root = current 20th-smallest score
    if (sc < hD[tid]) {
        int node = 0;
        while (true) {
            int l = 2 * node + 1, r = 2 * node + 2;
            int big = node;
            float bd = sc;
            if (l < KK) {
                float ld = hD[l * 128 + tid];
                if (ld > bd) { bd = ld; big = l; }
            }
            if (r < KK) {
                float rd = hD[r * 128 + tid];
                if (rd > bd) { bd = rd; big = r; }
            }
            if (big == node) break;
            hD[node * 128 + tid] = hD[big * 128 + tid];
            hI[node * 128 + tid] = hI[big * 128 + tid];
            node = big;
        }
        hD[node * 128 + tid] = sc;
        hI[node * 128 + tid] = c;
    }
}

__global__ void __launch_bounds__(128) knn_kernel(const float* __restrict__ x) {
    const int b = blockIdx.y;
    const int tid = threadIdx.x;
    const int r = blockIdx.x * 128 + tid;

    __shared__ float4 xs4[CC][16];     // 64 ch x 64 cols tile (16KB)
    __shared__ float  sqs[64];
    __shared__ float  hD[KK][128];     // per-thread heaps, stride-128 => conflict-free
    __shared__ int    hI[KK][128];

    const float* xb = x + (size_t)b * CC * NN;

    float xr[CC];
#pragma unroll
    for (int ch = 0; ch < CC; ch++) xr[ch] = xb[(size_t)ch * NN + r];

#pragma unroll
    for (int j = 0; j < KK; j++) { hD[j][tid] = 3.0e38f; hI[j][tid] = 0; }

    float* hD0 = &hD[0][0];
    int*   hI0 = &hI[0][0];

    for (int tile = 0; tile < NN / 64; tile++) {
        int col0 = tile * 64;
        __syncthreads();
        // cooperative tile load: 64x64 floats = 1024 float4, coalesced
        for (int i = tid; i < 1024; i += 128) {
            int ch = i >> 4, cg = i & 15;
            xs4[ch][cg] = *reinterpret_cast<const float4*>(xb + (size_t)ch * NN + col0 + cg * 4);
        }
        if (tid < 64) sqs[tid] = g_sq[b * NN + col0 + tid];
        __syncthreads();

        for (int cg = 0; cg < 16; cg++) {
            float a0 = 0.f, a1 = 0.f, a2 = 0.f, a3 = 0.f;
#pragma unroll
            for (int ch = 0; ch < CC; ch++) {
                float4 s4 = xs4[ch][cg];     // broadcast LDS.128
                float xv = xr[ch];
                a0 = fmaf(xv, s4.x, a0);
                a1 = fmaf(xv, s4.y, a1);
                a2 = fmaf(xv, s4.z, a2);
                a3 = fmaf(xv, s4.w, a3);
            }
            int cb = col0 + cg * 4;
            // score = ||x_c||^2 - 2<x_r, x_c>  (row-constant term dropped; same ordering)
            heap_insert(sqs[cg * 4 + 0] - 2.f * a0, cb + 0, hD0, hI0, tid);
            heap_insert(sqs[cg * 4 + 1] - 2.f * a1, cb + 1, hD0, hI0, tid);
            heap_insert(sqs[cg * 4 + 2] - 2.f * a2, cb + 2, hD0, hI0, tid);
            heap_insert(sqs[cg * 4 + 3] - 2.f * a3, cb + 3, hD0, hI0, tid);
        }
    }

#pragma unroll
    for (int j = 0; j < KK; j++) g_idx[((size_t)b * NN + r) * KK + j] = hI[j][tid];
}

// ---------------- kernel C: u = W1 @ x, v = (W2-W1) @ x (point-major) ----------------
__global__ void __launch_bounds__(128) gemm_uv_kernel(const float* __restrict__ x,
                                                      const float* __restrict__ W) {
    int b = blockIdx.z, og = blockIdx.y;
    int n = blockIdx.x * 128 + threadIdx.x;

    __shared__ float W1s[16][64];
    __shared__ float Wds[16][64];
    for (int i = threadIdx.x; i < 16 * 64; i += 128) {
        int oo = i >> 6, c = i & 63;
        int o = og * 16 + oo;
        float w1 = W[o * 2 * CC + c];
        float w2 = W[o * 2 * CC + CC + c];
        W1s[oo][c] = w1;
        Wds[oo][c] = w2 - w1;
    }
    __syncthreads();

    float ua[16], va[16];
#pragma unroll
    for (int oo = 0; oo < 16; oo++) { ua[oo] = 0.f; va[oo] = 0.f; }

    const float* xb = x + (size_t)b * CC * NN + n;
#pragma unroll
    for (int ch = 0; ch < CC; ch++) {
        float xv = xb[(size_t)ch * NN];
#pragma unroll
        for (int oo = 0; oo < 16; oo++) {
            ua[oo] = fmaf(W1s[oo][ch], xv, ua[oo]);
            va[oo] = fmaf(Wds[oo][ch], xv, va[oo]);
        }
    }

    float* up = g_u + ((size_t)b * NN + n) * OUTC + og * 16;
    float* vp = g_v + ((size_t)b * NN + n) * OUTC + og * 16;
#pragma unroll
    for (int oo = 0; oo < 16; oo += 4) {
        *reinterpret_cast<float4*>(up + oo) = make_float4(ua[oo], ua[oo + 1], ua[oo + 2], ua[oo + 3]);
        *reinterpret_cast<float4*>(vp + oo) = make_float4(va[oo], va[oo + 1], va[oo + 2], va[oo + 3]);
    }
}

// ---------------- kernel D: per-edge z = u[j]+v[i]; max/min over k; BN stats ----------------
__global__ void __launch_bounds__(256) edge_kernel() {
    __shared__ float ssum[OUTC];
    __shared__ float ssq[OUTC];
    int tid = threadIdx.x, lane = tid & 31, wrp = tid >> 5;
    if (tid < OUTC) { ssum[tid] = 0.f; ssq[tid] = 0.f; }
    __syncthreads();

    int p0 = blockIdx.x * 64;           // 64 points per block, 8 per warp
    float lsum0 = 0.f, lsq0 = 0.f, lsum1 = 0.f, lsq1 = 0.f;

    for (int i = 0; i < 8; i++) {
        int p = p0 + wrp * 8 + i;
        const float* vp = g_v + (size_t)p * OUTC;
        float v0 = vp[lane], v1 = vp[lane + 32];
        int idxv = 0;
        if (lane < KK) idxv = g_idx[(size_t)p * KK + lane];
        int bbase = (p >> 12) << 12;    // b * N

        float mx0 = -3.0e38f, mn0 = 3.0e38f, mx1 = -3.0e38f, mn1 = 3.0e38f;
#pragma unroll
        for (int k = 0; k < KK; k++) {
            int j = __shfl_sync(0xffffffffu, idxv, k);
            const float* uj = g_u + (size_t)(bbase + j) * OUTC;
            float z0 = uj[lane] + v0;
            float z1 = uj[lane + 32] + v1;
            mx0 = fmaxf(mx0, z0); mn0 = fminf(mn0, z0);
            mx1 = fmaxf(mx1, z1); mn1 = fminf(mn1, z1);
            lsum0 += z0; lsq0 = fmaf(z0, z0, lsq0);
            lsum1 += z1; lsq1 = fmaf(z1, z1, lsq1);
        }
        float* mxp = g_mx + (size_t)p * OUTC;
        float* mnp = g_mn + (size_t)p * OUTC;
        mxp[lane] = mx0; mxp[lane + 32] = mx1;
        mnp[lane] = mn0; mnp[lane + 32] = mn1;
    }

    atomicAdd(&ssum[lane], lsum0);
    atomicAdd(&ssum[lane + 32], lsum1);
    atomicAdd(&ssq[lane], lsq0);
    atomicAdd(&ssq[lane + 32], lsq1);
    __syncthreads();
    if (tid < OUTC) {
        atomicAdd(&g_sum[tid], ssum[tid]);
        atomicAdd(&g_sumsq[tid], ssq[tid]);
    }
}

// ---------------- kernel E0: finalize BN affine ----------------
__global__ void stats_kernel(const float* __restrict__ gamma, const float* __restrict__ beta) {
    int o = threadIdx.x;
    const float cnt = (float)((size_t)BB * NN * KK);
    float mean = g_sum[o] / cnt;
    float var = g_sumsq[o] / cnt - mean * mean;
    float s = gamma[o] * rsqrtf(var + 1e-5f);
    g_s[o] = s;
    g_t[o] = fmaf(-mean, s, beta[o]);
}

// ---------------- kernel E: BN + LeakyReLU + transpose to [B,O,N] ----------------
__global__ void __launch_bounds__(256) out_kernel(float* __restrict__ out) {
    __shared__ float tile[64][65];
    __shared__ float ss[OUTC], tt[OUTC];
    int tid = threadIdx.x;
    if (tid < OUTC) { ss[tid] = g_s[tid]; tt[tid] = g_t[tid]; }
    __syncthreads();

    int p0 = blockIdx.x * 64;
    int b = p0 >> 12;
    int n0 = p0 & (NN - 1);

#pragma unroll
    for (int j = 0; j < 16; j++) {
        int i = tid + j * 256;
        int nn = i >> 6, o = i & 63;          // consecutive tid -> consecutive o (coalesced read)
        size_t base = (size_t)(p0 + nn) * OUTC + o;
        float s = ss[o];
        float z = (s >= 0.f) ? g_mx[base] : g_mn[base];
        float y = fmaf(s, z, tt[o]);
        y = (y >= 0.f) ? y : 0.2f * y;
        tile[o][nn] = y;
    }
    __syncthreads();
#pragma unroll
    for (int j = 0; j < 16; j++) {
        int i = tid + j * 256;
        int o = i >> 6, nn = i & 63;          // consecutive tid -> consecutive n (coalesced write)
        out[((size_t)(b * OUTC + o)) * NN + n0 + nn] = tile[o][nn];
    }
}

// ---------------- launch ----------------
extern "C" void kernel_launch(void* const* d_in, const int* in_sizes, int n_in,
                              void* d_out, int out_size) {
    const float* x     = (const float*)d_in[0];
    const float* W     = (const float*)d_in[1];
    const float* gamma = (const float*)d_in[2];
    const float* beta  = (const float*)d_in[3];
    float* out = (float*)d_out;

    prep_kernel<<<(BB * NN) / 128, 128>>>(x);
    knn_kernel<<<dim3(NN / 128, BB), 128>>>(x);
    gemm_uv_kernel<<<dim3(NN / 128, 4, BB), 128>>>(x, W);
    edge_kernel<<<(BB * NN) / 64, 256>>>();
    stats_kernel<<<1, OUTC>>>(gamma, beta);
    out_kernel<<<(BB * NN) / 64, 256>>>(out);
}

// round 3
// speedup vs baseline: 1.2227x; 1.2227x over previous
#include <cuda_runtime.h>
#include <cuda_fp16.h>
#include <cstdint>

#define BB 8
#define CC 64
#define NN 4096
#define KK 20
#define OUTC 64
#define TM 128
#define TN 64

// ===================== device scratch (allocation-free) =====================
__device__ __half g_hi[(size_t)BB * NN * CC];
__device__ __half g_lo[(size_t)BB * NN * CC];
__device__ float g_sq[BB * NN];
__device__ int   g_idx[BB * NN * KK];
__device__ float g_u[(size_t)BB * NN * OUTC];
__device__ float g_v[(size_t)BB * NN * OUTC];
__device__ float g_mx[(size_t)BB * NN * OUTC];
__device__ float g_mn[(size_t)BB * NN * OUTC];
__device__ float g_sum[OUTC];
__device__ float g_sumsq[OUTC];
__device__ float g_s[OUTC];
__device__ float g_t[OUTC];

// ===================== mma / ldmatrix helpers (sm_80+ baseline) =====================
__device__ __forceinline__ void ldsm_x4(uint32_t addr, uint32_t* r) {
    asm volatile("ldmatrix.sync.aligned.m8n8.x4.shared.b16 {%0,%1,%2,%3}, [%4];"
                 : "=r"(r[0]), "=r"(r[1]), "=r"(r[2]), "=r"(r[3]) : "r"(addr));
}
__device__ __forceinline__ void mma16816(float* d, const uint32_t* a, const uint32_t* b) {
    asm volatile("mma.sync.aligned.m16n8k16.row.col.f32.f16.f16.f32 "
                 "{%0,%1,%2,%3}, {%4,%5,%6,%7}, {%8,%9}, {%0,%1,%2,%3};"
                 : "+f"(d[0]), "+f"(d[1]), "+f"(d[2]), "+f"(d[3])
                 : "r"(a[0]), "r"(a[1]), "r"(a[2]), "r"(a[3]), "r"(b[0]), "r"(b[1]));
}
__device__ __forceinline__ uint32_t smem_u32(const void* p) {
    uint32_t a;
    asm("{ .reg .u64 t; cvta.to.shared.u64 t, %1; cvt.u32.u64 %0, t; }" : "=r"(a) : "l"(p));
    return a;
}

// ===================== kernel A: sq norms + fp16 hi/lo split =====================
__global__ void __launch_bounds__(128) prep_kernel(const float* __restrict__ x) {
    int p = blockIdx.x * 128 + threadIdx.x;
    int b = p >> 12;
    int n = p & (NN - 1);
    const float* xb = x + (size_t)b * CC * NN + n;
    float s = 0.f;
#pragma unroll
    for (int g = 0; g < 8; g++) {
        uint4 h4, l4;
        unsigned short* hp = (unsigned short*)&h4;
        unsigned short* lp = (unsigned short*)&l4;
#pragma unroll
        for (int e = 0; e < 8; e++) {
            float v = xb[(size_t)(g * 8 + e) * NN];
            s = fmaf(v, v, s);
            __half h = __float2half_rn(v);
            __half l = __float2half_rn(v - __half2float(h));
            hp[e] = __half_as_ushort(h);
            lp[e] = __half_as_ushort(l);
        }
        *reinterpret_cast<uint4*>(g_hi + (size_t)p * CC + g * 8) = h4;
        *reinterpret_cast<uint4*>(g_lo + (size_t)p * CC + g * 8) = l4;
    }
    g_sq[p] = s;
    if (blockIdx.x == 0 && threadIdx.x < OUTC) {
        g_sum[threadIdx.x] = 0.f;
        g_sumsq[threadIdx.x] = 0.f;
    }
}

// ===================== kernel B: mma.sync distance GEMM + fused top-K =====================
// dynamic smem layout (bytes); A/B padded row stride 72 halves (144B) for conflict-free ldmatrix
#define SM_A_HI  0          /* 128*144 = 18432 */
#define SM_A_LO  18432      /* 18432 */
#define SM_B_HI  36864      /* 64*144 = 9216 */
#define SM_B_LO  46080      /* 9216 */
#define SM_DST   55296      /* 128*66*4 = 33792 */
#define SM_SQS   89088      /* 2*64*4 = 512 */
#define SM_HD    89600      /* 20*256*4 = 20480 */
#define SM_HIX   110080     /* 20480 */
#define SM_TOTAL 130560

__device__ __forceinline__ void heap_insert(float sc, int c, float* hD, int* hI, int tid) {
    int node = 0;
    while (true) {
        int l = 2 * node + 1, r = 2 * node + 2;
        int big = node;
        float bd = sc;
        if (l < KK) { float ld = hD[l * 256 + tid]; if (ld > bd) { bd = ld; big = l; } }
        if (r < KK) { float rd = hD[r * 256 + tid]; if (rd > bd) { bd = rd; big = r; } }
        if (big == node) break;
        hD[node * 256 + tid] = hD[big * 256 + tid];
        hI[node * 256 + tid] = hI[big * 256 + tid];
        node = big;
    }
    hD[node * 256 + tid] = sc;
    hI[node * 256 + tid] = c;
}

__global__ void __launch_bounds__(256, 1) knn_mma_kernel() {
    extern __shared__ char sm[];
    const uint32_t smb = smem_u32(sm);
    const int tid = threadIdx.x;
    const int wid = tid >> 5;
    const int lane = tid & 31;
    const int b = blockIdx.y;
    const int row0 = blockIdx.x * TM;

    const __half* hi_b = g_hi + (size_t)b * NN * CC;
    const __half* lo_b = g_lo + (size_t)b * NN * CC;
    float* Dst = (float*)(sm + SM_DST);
    float* sqs = (float*)(sm + SM_SQS);
    float* hD  = (float*)(sm + SM_HD);
    int*   hI  = (int*)(sm + SM_HIX);

    // ---- load A rows (this CTA's 128 points), hi+lo, padded stride 144B ----
    for (int i = tid; i < 2048; i += 256) {
        int m = (i & 1023) >> 3, j = i & 7;
        const __half* src = (i < 1024) ? hi_b : lo_b;
        char* dstbase = sm + ((i < 1024) ? SM_A_HI : SM_A_LO);
        *reinterpret_cast<uint4*>(dstbase + m * 144 + j * 16) =
            *reinterpret_cast<const uint4*>(src + (size_t)(row0 + m) * CC + j * 8);
    }
    // ---- init heaps ----
#pragma unroll
    for (int j = 0; j < KK; j++) { hD[j * 256 + tid] = 3.0e38f; hI[j * 256 + tid] = 0; }
    float rootD = 3.0e38f;

    // ---- B tile 0 into smem ----
    uint4 pre[4];
    {
        int col0 = 0;
#pragma unroll
        for (int t = 0; t < 4; t++) {
            int i = tid + t * 256;
            int n = (i & 511) >> 3, j = i & 7;
            const __half* src = (i < 512) ? hi_b : lo_b;
            pre[t] = *reinterpret_cast<const uint4*>(src + (size_t)(col0 + n) * CC + j * 8);
        }
#pragma unroll
        for (int t = 0; t < 4; t++) {
            int i = tid + t * 256;
            int n = (i & 511) >> 3, j = i & 7;
            char* dstb = sm + ((i < 512) ? SM_B_HI : SM_B_LO);
            *reinterpret_cast<uint4*>(dstb + n * 144 + j * 16) = pre[t];
        }
        if (tid < 64) sqs[tid] = g_sq[b * NN + tid];
    }
    __syncthreads();

    const int m0 = wid * 16;
    const int erow = tid & 127;
    const int ech = tid >> 7;            // which 32-col half this thread owns

    for (int ct = 0; ct < NN / TN; ct++) {
        int buf = ct & 1;

        // prefetch next B tile to registers (overlaps with MMA)
        if (ct + 1 < NN / TN) {
            int col0 = (ct + 1) * TN;
#pragma unroll
            for (int t = 0; t < 4; t++) {
                int i = tid + t * 256;
                int n = (i & 511) >> 3, j = i & 7;
                const __half* src = (i < 512) ? hi_b : lo_b;
                pre[t] = *reinterpret_cast<const uint4*>(src + (size_t)(col0 + n) * CC + j * 8);
            }
        }

        // ---- MMA: D[128x64] = A(128x64) . B^T(64x64), 3 passes hi/lo ----
        float acc[8][4];
#pragma unroll
        for (int nt = 0; nt < 8; nt++)
#pragma unroll
            for (int e = 0; e < 4; e++) acc[nt][e] = 0.f;

#pragma unroll
        for (int ks = 0; ks < 4; ks++) {
            uint32_t ah[4], al[4];
            uint32_t aoff = (uint32_t)(m0 + (lane & 15)) * 144u +
                            (uint32_t)(ks * 16 + ((lane >> 4) << 3)) * 2u;
            ldsm_x4(smb + SM_A_HI + aoff, ah);
            ldsm_x4(smb + SM_A_LO + aoff, al);
#pragma unroll
            for (int ntp = 0; ntp < 4; ntp++) {
                uint32_t bh[4], bl[4];
                uint32_t bn = (uint32_t)(ntp * 16 + ((lane >> 4) << 3) + (lane & 7));
                uint32_t bk = (uint32_t)(ks * 16 + (((lane >> 3) & 1) << 3));
                uint32_t boff = bn * 144u + bk * 2u;
                ldsm_x4(smb + SM_B_HI + boff, bh);
                ldsm_x4(smb + SM_B_LO + boff, bl);
                mma16816(acc[2 * ntp],     ah, bh);
                mma16816(acc[2 * ntp + 1], ah, bh + 2);
                mma16816(acc[2 * ntp],     ah, bl);
                mma16816(acc[2 * ntp + 1], ah, bl + 2);
                mma16816(acc[2 * ntp],     al, bh);
                mma16816(acc[2 * ntp + 1], al, bh + 2);
            }
        }

        __syncthreads();   // all warps done reading B smem; prev epilogue done reading Dst

        // store next B tile to smem
        if (ct + 1 < NN / TN) {
#pragma unroll
            for (int t = 0; t < 4; t++) {
                int i = tid + t * 256;
                int n = (i & 511) >> 3, j = i & 7;
                char* dstb = sm + ((i < 512) ? SM_B_HI : SM_B_LO);
                *reinterpret_cast<uint4*>(dstb + n * 144 + j * 16) = pre[t];
            }
            if (tid < 64) sqs[(buf ^ 1) * 64 + tid] = g_sq[b * NN + (ct + 1) * TN + tid];
        }

        // stage D to smem (stride 66 floats)
        {
            int g = lane >> 2, t4 = lane & 3;
#pragma unroll
            for (int nt = 0; nt < 8; nt++) {
                int c0 = nt * 8 + t4 * 2;
                *reinterpret_cast<float2*>(Dst + (m0 + g) * 66 + c0)     = make_float2(acc[nt][0], acc[nt][1]);
                *reinterpret_cast<float2*>(Dst + (m0 + g + 8) * 66 + c0) = make_float2(acc[nt][2], acc[nt][3]);
            }
        }
        __syncthreads();

        // ---- epilogue: scores + heap ----
        {
            const float* dr = Dst + erow * 66 + ech * 32;
            const float* sq = sqs + buf * 64 + ech * 32;
            int colg = ct * TN + ech * 32;
#pragma unroll
            for (int j = 0; j < 16; j++) {
                float2 d = *reinterpret_cast<const float2*>(dr + j * 2);
                float sc0 = fmaf(-2.f, d.x, sq[j * 2]);
                float sc1 = fmaf(-2.f, d.y, sq[j * 2 + 1]);
                if (sc0 < rootD) { heap_insert(sc0, colg + j * 2, hD, hI, tid); rootD = hD[tid]; }
                if (sc1 < rootD) { heap_insert(sc1, colg + j * 2 + 1, hD, hI, tid); rootD = hD[tid]; }
            }
        }
    }

    __syncthreads();
    // ---- merge the two half-heaps per row, write indices ----
    if (tid < 128) {
#pragma unroll
        for (int j = 0; j < KK; j++) {
            float sc = hD[j * 256 + tid + 128];
            if (sc < hD[tid]) heap_insert(sc, hI[j * 256 + tid + 128], hD, hI, tid);
        }
#pragma unroll
        for (int j = 0; j < KK; j++)
            g_idx[((size_t)b * NN + row0 + tid) * KK + j] = hI[j * 256 + tid];
    }
}

// ===================== kernel C: u = W1 @ x, v = (W2-W1) @ x =====================
__global__ void __launch_bounds__(128) gemm_uv_kernel(const float* __restrict__ x,
                                                      const float* __restrict__ W) {
    int b = blockIdx.z, og = blockIdx.y;
    int n = blockIdx.x * 128 + threadIdx.x;

    __shared__ float W1s[16][64];
    __shared__ float Wds[16][64];
    for (int i = threadIdx.x; i < 16 * 64; i += 128) {
        int oo = i >> 6, c = i & 63;
        int o = og * 16 + oo;
        float w1 = W[o * 2 * CC + c];
        float w2 = W[o * 2 * CC + CC + c];
        W1s[oo][c] = w1;
        Wds[oo][c] = w2 - w1;
    }
    __syncthreads();

    float ua[16], va[16];
#pragma unroll
    for (int oo = 0; oo < 16; oo++) { ua[oo] = 0.f; va[oo] = 0.f; }

    const float* xb = x + (size_t)b * CC * NN + n;
#pragma unroll
    for (int ch = 0; ch < CC; ch++) {
        float xv = xb[(size_t)ch * NN];
#pragma unroll
        for (int oo = 0; oo < 16; oo++) {
            ua[oo] = fmaf(W1s[oo][ch], xv, ua[oo]);
            va[oo] = fmaf(Wds[oo][ch], xv, va[oo]);
        }
    }

    float* up = g_u + ((size_t)b * NN + n) * OUTC + og * 16;
    float* vp = g_v + ((size_t)b * NN + n) * OUTC + og * 16;
#pragma unroll
    for (int oo = 0; oo < 16; oo += 4) {
        *reinterpret_cast<float4*>(up + oo) = make_float4(ua[oo], ua[oo + 1], ua[oo + 2], ua[oo + 3]);
        *reinterpret_cast<float4*>(vp + oo) = make_float4(va[oo], va[oo + 1], va[oo + 2], va[oo + 3]);
    }
}

// ===================== kernel D: edges: z = u[j]+v[i]; max/min; BN stats =====================
__global__ void __launch_bounds__(256) edge_kernel() {
    __shared__ float ssum[OUTC];
    __shared__ float ssq[OUTC];
    int tid = threadIdx.x, lane = tid & 31, wrp = tid >> 5;
    if (tid < OUTC) { ssum[tid] = 0.f; ssq[tid] = 0.f; }
    __syncthreads();

    int p0 = blockIdx.x * 64;
    float lsum0 = 0.f, lsq0 = 0.f, lsum1 = 0.f, lsq1 = 0.f;

    for (int i = 0; i < 8; i++) {
        int p = p0 + wrp * 8 + i;
        const float* vp = g_v + (size_t)p * OUTC;
        float v0 = vp[lane], v1 = vp[lane + 32];
        int idxv = 0;
        if (lane < KK) idxv = g_idx[(size_t)p * KK + lane];
        int bbase = (p >> 12) << 12;

        float mx0 = -3.0e38f, mn0 = 3.0e38f, mx1 = -3.0e38f, mn1 = 3.0e38f;
#pragma unroll
        for (int k = 0; k < KK; k++) {
            int j = __shfl_sync(0xffffffffu, idxv, k);
            const float* uj = g_u + (size_t)(bbase + j) * OUTC;
            float z0 = uj[lane] + v0;
            float z1 = uj[lane + 32] + v1;
            mx0 = fmaxf(mx0, z0); mn0 = fminf(mn0, z0);
            mx1 = fmaxf(mx1, z1); mn1 = fminf(mn1, z1);
            lsum0 += z0; lsq0 = fmaf(z0, z0, lsq0);
            lsum1 += z1; lsq1 = fmaf(z1, z1, lsq1);
        }
        float* mxp = g_mx + (size_t)p * OUTC;
        float* mnp = g_mn + (size_t)p * OUTC;
        mxp[lane] = mx0; mxp[lane + 32] = mx1;
        mnp[lane] = mn0; mnp[lane + 32] = mn1;
    }

    atomicAdd(&ssum[lane], lsum0);
    atomicAdd(&ssum[lane + 32], lsum1);
    atomicAdd(&ssq[lane], lsq0);
    atomicAdd(&ssq[lane + 32], lsq1);
    __syncthreads();
    if (tid < OUTC) {
        atomicAdd(&g_sum[tid], ssum[tid]);
        atomicAdd(&g_sumsq[tid], ssq[tid]);
    }
}

// ===================== kernel E0: finalize BN affine =====================
__global__ void stats_kernel(const float* __restrict__ gamma, const float* __restrict__ beta) {
    int o = threadIdx.x;
    const float cnt = (float)((size_t)BB * NN * KK);
    float mean = g_sum[o] / cnt;
    float var = g_sumsq[o] / cnt - mean * mean;
    float s = gamma[o] * rsqrtf(var + 1e-5f);
    g_s[o] = s;
    g_t[o] = fmaf(-mean, s, beta[o]);
}

// ===================== kernel E: BN + LeakyReLU + transpose to [B,O,N] =====================
__global__ void __launch_bounds__(256) out_kernel(float* __restrict__ out) {
    __shared__ float tile[64][65];
    __shared__ float ss[OUTC], tt[OUTC];
    int tid = threadIdx.x;
    if (tid < OUTC) { ss[tid] = g_s[tid]; tt[tid] = g_t[tid]; }
    __syncthreads();

    int p0 = blockIdx.x * 64;
    int b = p0 >> 12;
    int n0 = p0 & (NN - 1);

#pragma unroll
    for (int j = 0; j < 16; j++) {
        int i = tid + j * 256;
        int nn = i >> 6, o = i & 63;
        size_t base = (size_t)(p0 + nn) * OUTC + o;
        float s = ss[o];
        float z = (s >= 0.f) ? g_mx[base] : g_mn[base];
        float y = fmaf(s, z, tt[o]);
        y = (y >= 0.f) ? y : 0.2f * y;
        tile[o][nn] = y;
    }
    __syncthreads();
#pragma unroll
    for (int j = 0; j < 16; j++) {
        int i = tid + j * 256;
        int o = i >> 6, nn = i & 63;
        out[((size_t)(b * OUTC + o)) * NN + n0 + nn] = tile[o][nn];
    }
}

// ===================== launch =====================
extern "C" void kernel_launch(void* const* d_in, const int* in_sizes, int n_in,
                              void* d_out, int out_size) {
    const float* x     = (const float*)d_in[0];
    const float* W     = (const float*)d_in[1];
    const float* gamma = (const float*)d_in[2];
    const float* beta  = (const float*)d_in[3];
    float* out = (float*)d_out;

    cudaFuncSetAttribute(knn_mma_kernel, cudaFuncAttributeMaxDynamicSharedMemorySize, SM_TOTAL);

    prep_kernel<<<(BB * NN) / 128, 128>>>(x);
    knn_mma_kernel<<<dim3(NN / TM, BB), 256, SM_TOTAL>>>();
    gemm_uv_kernel<<<dim3(NN / 128, 4, BB), 128>>>(x, W);
    edge_kernel<<<(BB * NN) / 64, 256>>>();
    stats_kernel<<<1, OUTC>>>(gamma, beta);
    out_kernel<<<(BB * NN) / 64, 256>>>(out);
}